// round 9
// baseline (speedup 1.0000x reference)
#include <cuda_runtime.h>
#include <cstdint>
#include <cstddef>

#define T_DIM 2048
#define B_DIM 32
#define E_DIM 512
#define N_DIM 512
#define K_DIM 512
#define M_DIM (T_DIM * B_DIM)   // 65536 rows, row m = t*B + b

// ---------------- device scratch ----------------
__device__ float g_w[M_DIM];
__device__ int   g_len[B_DIM];
__device__ int   g_nrows[B_DIM];
__device__ int   g_rt0[B_DIM * T_DIM];
__device__ int   g_rt1[B_DIM * T_DIM];
__device__ float g_rc0[B_DIM * T_DIM];
__device__ float g_rc1[B_DIM * T_DIM];
__device__ float g_rmult[B_DIM * T_DIM];
__device__ int   g_rowmap[M_DIM];   // compacted active rows -> m = t*B+b
__device__ int   g_R;               // number of active rows

// ---------------- f32x2 helpers ----------------
typedef unsigned long long u64;
__device__ __forceinline__ u64 fma2(u64 a, u64 b, u64 c) {
    u64 d;
    asm("fma.rn.f32x2 %0, %1, %2, %3;" : "=l"(d) : "l"(a), "l"(b), "l"(c));
    return d;
}
__device__ __forceinline__ u64 dupf(float a) {
    u64 d;
    asm("mov.b64 %0, {%1, %1};" : "=l"(d) : "f"(a));
    return d;
}
__device__ __forceinline__ void unpk(u64 v, float& lo, float& hi) {
    asm("mov.b64 {%0, %1}, %2;" : "=f"(lo), "=f"(hi) : "l"(v));
}

// ---------------- K0: mask detect + lengths + compacted rowmap --------------
__global__ void k0_mask(const void* __restrict__ mask) {
    __shared__ int flags[3];
    __shared__ int s_len[32], s_off[33];
    int tid = threadIdx.x;
    if (tid < 3) flags[tid] = 0;
    __syncthreads();
    const unsigned* dw = (const unsigned*)mask;
    for (int i = tid; i < 16384; i += blockDim.x) {
        unsigned d = dw[i];
        if (d != 0u) {
            if (d == 1u)                flags[0] = 1;
            else if (d == 0x3F800000u)  flags[1] = 1;
            else                        flags[2] = 1;
        }
    }
    __syncthreads();
    int kind = flags[2] ? 2 : (flags[1] ? 1 : 0);
    int warp = tid >> 5, lane = tid & 31;
    int cnt = 0;
    if (kind == 2) {
        const unsigned char* p = (const unsigned char*)mask + warp * T_DIM;
        for (int t = lane; t < T_DIM; t += 32) cnt += (p[t] == 0);
    } else {
        const unsigned* p = dw + (size_t)warp * T_DIM;
        for (int t = lane; t < T_DIM; t += 32) cnt += (p[t] == 0u);
    }
    for (int o = 16; o > 0; o >>= 1) cnt += __shfl_down_sync(0xffffffffu, cnt, o);
    if (lane == 0) { g_len[warp] = cnt; s_len[warp] = cnt; }
    __syncthreads();
    if (tid == 0) {
        int acc = 0;
        for (int b = 0; b < B_DIM; b++) { s_off[b] = acc; acc += s_len[b]; }
        s_off[32] = acc;
        g_R = acc;
    }
    __syncthreads();
    const int R = s_off[32];
    for (int b = 0; b < B_DIM; b++) {
        const int L = s_len[b], o = s_off[b];
        for (int t = tid; t < L; t += 1024) g_rowmap[o + t] = t * B_DIM + b;
    }
    for (int i = R + tid; i < M_DIM; i += 1024) g_rowmap[i] = 0;
}

// ---------------- K1: fused fp32 GEMM over compacted rows -------------------
#define BMT 128
#define BNT 128
#define BKT 16
#define KTILES (K_DIM / BKT)   // 32
#define AS_STR (BMT + 4)

__global__ __launch_bounds__(256, 2) void k1_gemm(
    const float* __restrict__ A,   // [T][B][E]; row m at m*E
    const float* __restrict__ W1,  // [K][N] row-major
    const float* __restrict__ b1,  // [N]
    const float* __restrict__ w2,  // [N]
    const float* __restrict__ b2)  // [1]
{
    const int t0 = blockIdx.x * BMT;
    const int R = g_R;
    if (t0 >= R) return;           // tile entirely past the active rows

    __shared__ float As[2][BKT][AS_STR];
    __shared__ __align__(16) float Bs[2][BKT][BNT];
    __shared__ float red[BMT][17];

    const int tid = threadIdx.x;
    const int tx = tid & 15, ty = tid >> 4;

    const int aRow0 = tid >> 2;
    const int aRow1 = aRow0 + 64;
    const int aCol  = (tid & 3) * 4;
    const int bRow0 = tid >> 5;
    const int bRow1 = bRow0 + 8;
    const int bCol  = (tid & 31) * 4;

    // compacted-row indirection (hoisted; rows past R read row 0, never write)
    const int m0r = g_rowmap[t0 + aRow0];
    const int m1r = g_rowmap[t0 + aRow1];
    const float* aP0 = A + (size_t)m0r * K_DIM + aCol;
    const float* aP1 = A + (size_t)m1r * K_DIM + aCol;

    float rowacc[8];
#pragma unroll
    for (int i = 0; i < 8; i++) rowacc[i] = 0.f;
    const float b2s = b2[0];

    for (int n0 = 0; n0 < N_DIM; n0 += BNT) {
        u64 acc2[8][4];
#pragma unroll
        for (int i = 0; i < 8; i++)
#pragma unroll
            for (int j = 0; j < 4; j++) acc2[i][j] = 0ull;

        float4 aR0, aR1, bR0, bR1;
        aR0 = *(const float4*)(aP0);
        aR1 = *(const float4*)(aP1);
        bR0 = *(const float4*)(W1 + (size_t)bRow0 * N_DIM + n0 + bCol);
        bR1 = *(const float4*)(W1 + (size_t)bRow1 * N_DIM + n0 + bCol);
        As[0][aCol + 0][aRow0] = aR0.x; As[0][aCol + 1][aRow0] = aR0.y;
        As[0][aCol + 2][aRow0] = aR0.z; As[0][aCol + 3][aRow0] = aR0.w;
        As[0][aCol + 0][aRow1] = aR1.x; As[0][aCol + 1][aRow1] = aR1.y;
        As[0][aCol + 2][aRow1] = aR1.z; As[0][aCol + 3][aRow1] = aR1.w;
        *(float4*)&Bs[0][bRow0][bCol] = bR0;
        *(float4*)&Bs[0][bRow1][bCol] = bR1;
        __syncthreads();

        for (int kt = 0; kt < KTILES; kt++) {
            const int cur = kt & 1;
            if (kt + 1 < KTILES) {
                const int kb = (kt + 1) * BKT;
                aR0 = *(const float4*)(aP0 + kb);
                aR1 = *(const float4*)(aP1 + kb);
                bR0 = *(const float4*)(W1 + (size_t)(kb + bRow0) * N_DIM + n0 + bCol);
                bR1 = *(const float4*)(W1 + (size_t)(kb + bRow1) * N_DIM + n0 + bCol);
            }
#pragma unroll
            for (int kk = 0; kk < BKT; kk++) {
                float4 a0 = *(const float4*)&As[cur][kk][ty * 8];
                float4 a1 = *(const float4*)&As[cur][kk][ty * 8 + 4];
                const u64* bp = (const u64*)&Bs[cur][kk][tx * 8];
                u64 b0 = bp[0], b1v = bp[1], b2v = bp[2], b3 = bp[3];
                float av[8] = {a0.x, a0.y, a0.z, a0.w, a1.x, a1.y, a1.z, a1.w};
#pragma unroll
                for (int i = 0; i < 8; i++) {
                    u64 ad = dupf(av[i]);
                    acc2[i][0] = fma2(ad, b0,  acc2[i][0]);
                    acc2[i][1] = fma2(ad, b1v, acc2[i][1]);
                    acc2[i][2] = fma2(ad, b2v, acc2[i][2]);
                    acc2[i][3] = fma2(ad, b3,  acc2[i][3]);
                }
            }
            if (kt + 1 < KTILES) {
                const int nb = cur ^ 1;
                As[nb][aCol + 0][aRow0] = aR0.x; As[nb][aCol + 1][aRow0] = aR0.y;
                As[nb][aCol + 2][aRow0] = aR0.z; As[nb][aCol + 3][aRow0] = aR0.w;
                As[nb][aCol + 0][aRow1] = aR1.x; As[nb][aCol + 1][aRow1] = aR1.y;
                As[nb][aCol + 2][aRow1] = aR1.z; As[nb][aCol + 3][aRow1] = aR1.w;
                *(float4*)&Bs[nb][bRow0][bCol] = bR0;
                *(float4*)&Bs[nb][bRow1][bCol] = bR1;
                __syncthreads();
            }
        }

        float b1r[8], w2r[8];
#pragma unroll
        for (int j = 0; j < 8; j++) {
            b1r[j] = b1[n0 + tx * 8 + j];
            w2r[j] = w2[n0 + tx * 8 + j];
        }
#pragma unroll
        for (int i = 0; i < 8; i++)
#pragma unroll
            for (int j2 = 0; j2 < 4; j2++) {
                float clo, chi;
                unpk(acc2[i][j2], clo, chi);
                float h0 = fmaxf(clo + b1r[j2 * 2], 0.f);
                float h1 = fmaxf(chi + b1r[j2 * 2 + 1], 0.f);
                rowacc[i] = fmaf(h0, w2r[j2 * 2], rowacc[i]);
                rowacc[i] = fmaf(h1, w2r[j2 * 2 + 1], rowacc[i]);
            }
        __syncthreads();
    }

    // reduce rowacc across the 16 tx threads of each row (fixed order)
#pragma unroll
    for (int i = 0; i < 8; i++) red[ty * 8 + i][tx] = rowacc[i];
    __syncthreads();
    if (tid < BMT && t0 + tid < R) {
        float s = 0.f;
#pragma unroll
        for (int x = 0; x < 16; x++) s += red[tid][x];
        float arg = s + b2s;
        g_w[g_rowmap[t0 + tid]] = 1.0f / (1.0f + expf(-arg));
    }
}

// ---------------- K2: scalar CIF scan per batch -----------------------------
__global__ void k2_scan(float* __restrict__ out_marks,
                        float* __restrict__ out_quantity,
                        int write_extras)
{
    const int b = blockIdx.x;
    const int lane = threadIdx.x;
    const int L = g_len[b];

    float prev_w = 0.f, quantity = 0.f, seg_c0 = 0.f, last_w = 0.f;
    int seg_t0 = 0, r = 0;

    for (int chunk = 0; chunk < T_DIM; chunk += 32) {
        float wv = g_w[(chunk + lane) * B_DIM + b];
        float mymark = 0.f;
#pragma unroll 1
        for (int j = 0; j < 32; j++) {
            const int t = chunk + j;
            float w = __shfl_sync(0xffffffffu, wv, j);
            float mark = 0.f;
            if (t < L) {
                quantity += w;
                if (t == 0) seg_c0 = w;
                bool fired = (prev_w + w >= 1.0f);
                if (fired) {
                    float remained = 1.0f - prev_w;
                    if (lane == 0) {
                        int idx = b * T_DIM + r;
                        g_rt0[idx] = seg_t0; g_rt1[idx] = t;
                        g_rc0[idx] = seg_c0; g_rc1[idx] = remained;
                        g_rmult[idx] = 1.0f;
                    }
                    r++;
                    prev_w = w - remained;
                    seg_t0 = t;
                    seg_c0 = w - remained;
                    mark = 1.f;
                } else {
                    prev_w = w + prev_w;
                }
                last_w = w;
            } else if (t == L) {
                if (prev_w > 0.6f) {
                    if (lane == 0) {
                        int idx = b * T_DIM + r;
                        g_rt0[idx] = seg_t0; g_rt1[idx] = L - 1;
                        g_rc0[idx] = seg_c0; g_rc1[idx] = last_w;
                        g_rmult[idx] = 1.0f / (prev_w + 1e-10f);
                    }
                    r++;
                    mark = 1.f;
                }
            }
            if (lane == j) mymark = mark;
        }
        if (write_extras) out_marks[b * T_DIM + chunk + lane] = mymark;
    }
    if (lane == 0) {
        g_nrows[b] = r;
        if (write_extras) out_quantity[b] = quantity;
    }
}

// ---------------- K3: segment sums in compacted order -----------------------
__global__ __launch_bounds__(128) void k3_rows(
    const float* __restrict__ x,
    float* __restrict__ out_cif,
    float* __restrict__ out_mask,
    int write_extras)
{
    const int r = blockIdx.x, b = blockIdx.y;
    const int tid = threadIdx.x;
    const int nr = g_nrows[b];

    float4 acc = make_float4(0.f, 0.f, 0.f, 0.f);
    if (r < nr) {
        const int idx = b * T_DIM + r;
        const int t0 = g_rt0[idx], t1 = g_rt1[idx];
        const float c0 = g_rc0[idx], c1 = g_rc1[idx], mult = g_rmult[idx];
        const float* xb = x + (size_t)b * E_DIM + tid * 4;
        const size_t tstride = (size_t)B_DIM * E_DIM;

        float4 v = *(const float4*)(xb + (size_t)t0 * tstride);
        acc.x = c0 * v.x; acc.y = c0 * v.y; acc.z = c0 * v.z; acc.w = c0 * v.w;
        for (int t = t0 + 1; t < t1; t++) {
            float w = g_w[t * B_DIM + b];
            v = *(const float4*)(xb + (size_t)t * tstride);
            acc.x = fmaf(w, v.x, acc.x); acc.y = fmaf(w, v.y, acc.y);
            acc.z = fmaf(w, v.z, acc.z); acc.w = fmaf(w, v.w, acc.w);
        }
        if (t1 > t0) {
            v = *(const float4*)(xb + (size_t)t1 * tstride);
            acc.x = fmaf(c1, v.x, acc.x); acc.y = fmaf(c1, v.y, acc.y);
            acc.z = fmaf(c1, v.z, acc.z); acc.w = fmaf(c1, v.w, acc.w);
        }
        acc.x *= mult; acc.y *= mult; acc.z *= mult; acc.w *= mult;
    }
    *(float4*)(out_cif + ((size_t)(b * T_DIM + r)) * E_DIM + tid * 4) = acc;
    if (write_extras && tid == 0) out_mask[b * T_DIM + r] = (r < nr) ? 1.f : 0.f;
}

// ---------------- launch ----------------------------------------------------
extern "C" void kernel_launch(void* const* d_in, const int* in_sizes, int n_in,
                              void* d_out, int out_size)
{
    const float* enc = (const float*)d_in[0];
    const void*  mask = d_in[1];
    const float* dense_w = (const float*)d_in[2];
    const float* dense_b = (const float*)d_in[3];
    const float* wproj_w = (const float*)d_in[4];
    const float* wproj_b = (const float*)d_in[5];
    float* out = (float*)d_out;

    const int cif_elems = B_DIM * T_DIM * E_DIM;
    const int full = cif_elems + B_DIM * T_DIM + B_DIM + B_DIM * T_DIM;
    const int extras = (out_size >= full) ? 1 : 0;

    float* out_mask   = out + cif_elems;
    float* out_q      = out_mask + B_DIM * T_DIM;
    float* out_marks  = out_q + B_DIM;

    k0_mask<<<1, 1024>>>(mask);
    k1_gemm<<<M_DIM / BMT, 256>>>(enc, dense_w, dense_b, wproj_w, wproj_b);
    k2_scan<<<B_DIM, 32>>>(out_marks, out_q, extras);
    k3_rows<<<dim3(T_DIM, B_DIM), 128>>>(enc, out, out_mask, extras);
}

// round 10
// speedup vs baseline: 1.0045x; 1.0045x over previous
#include <cuda_runtime.h>
#include <cstdint>
#include <cstddef>

#define T_DIM 2048
#define B_DIM 32
#define E_DIM 512
#define N_DIM 512
#define K_DIM 512
#define M_DIM (T_DIM * B_DIM)   // 65536 rows, row m = t*B + b

// ---------------- device scratch ----------------
__device__ float g_w[M_DIM];
__device__ int   g_len[B_DIM];
__device__ int   g_off[B_DIM + 1];
__device__ int   g_nrows[B_DIM];
__device__ int   g_rt0[B_DIM * T_DIM];
__device__ int   g_rt1[B_DIM * T_DIM];
__device__ float g_rc0[B_DIM * T_DIM];
__device__ float g_rc1[B_DIM * T_DIM];
__device__ float g_rmult[B_DIM * T_DIM];
__device__ int   g_rowmap[M_DIM];   // compacted active rows -> m = t*B+b
__device__ int   g_R;               // number of active rows

// ---------------- f32x2 helpers ----------------
typedef unsigned long long u64;
__device__ __forceinline__ u64 fma2(u64 a, u64 b, u64 c) {
    u64 d;
    asm("fma.rn.f32x2 %0, %1, %2, %3;" : "=l"(d) : "l"(a), "l"(b), "l"(c));
    return d;
}
__device__ __forceinline__ u64 dupf(float a) {
    u64 d;
    asm("mov.b64 %0, {%1, %1};" : "=l"(d) : "f"(a));
    return d;
}
__device__ __forceinline__ void unpk(u64 v, float& lo, float& hi) {
    asm("mov.b64 {%0, %1}, %2;" : "=f"(lo), "=f"(hi) : "l"(v));
}

// ---------------- K0a: mask detect + lengths + prefix offsets ---------------
__global__ void k0a_mask(const void* __restrict__ mask) {
    __shared__ int flags[3];
    __shared__ int s_len[32];
    int tid = threadIdx.x;
    if (tid < 3) flags[tid] = 0;
    __syncthreads();
    const unsigned* dw = (const unsigned*)mask;
    for (int i = tid; i < 16384; i += blockDim.x) {
        unsigned d = dw[i];
        if (d != 0u) {
            if (d == 1u)                flags[0] = 1;
            else if (d == 0x3F800000u)  flags[1] = 1;
            else                        flags[2] = 1;
        }
    }
    __syncthreads();
    int kind = flags[2] ? 2 : (flags[1] ? 1 : 0);
    int warp = tid >> 5, lane = tid & 31;
    int cnt = 0;
    if (kind == 2) {
        const unsigned char* p = (const unsigned char*)mask + warp * T_DIM;
        for (int t = lane; t < T_DIM; t += 32) cnt += (p[t] == 0);
    } else {
        const unsigned* p = dw + (size_t)warp * T_DIM;
        for (int t = lane; t < T_DIM; t += 32) cnt += (p[t] == 0u);
    }
    for (int o = 16; o > 0; o >>= 1) cnt += __shfl_down_sync(0xffffffffu, cnt, o);
    if (lane == 0) { g_len[warp] = cnt; s_len[warp] = cnt; }
    __syncthreads();
    if (tid == 0) {
        int acc = 0;
        for (int b = 0; b < B_DIM; b++) { g_off[b] = acc; acc += s_len[b]; }
        g_off[B_DIM] = acc;
        g_R = acc;
    }
}

// ---------------- K0b: parallel rowmap fill ---------------------------------
// blocks 0..31: fill batch b's slice; block 32: zero-fill [R, R+256)
__global__ void k0b_rowmap() {
    const int b = blockIdx.x;
    if (b < B_DIM) {
        const int L = g_len[b], o = g_off[b];
        for (int t = threadIdx.x; t < L; t += 256)
            g_rowmap[o + t] = t * B_DIM + b;
    } else {
        const int i = g_R + threadIdx.x;
        if (i < M_DIM) g_rowmap[i] = 0;
    }
}

// ---------------- K1: fused fp32 GEMM over compacted rows -------------------
#define BMT 128
#define BNT 128
#define BKT 16
#define KTILES (K_DIM / BKT)   // 32
#define AS_STR (BMT + 4)

__global__ __launch_bounds__(256, 2) void k1_gemm(
    const float* __restrict__ A,   // [T][B][E]; row m at m*E
    const float* __restrict__ W1,  // [K][N] row-major
    const float* __restrict__ b1,  // [N]
    const float* __restrict__ w2,  // [N]
    const float* __restrict__ b2)  // [1]
{
    const int t0 = blockIdx.x * BMT;
    const int R = g_R;
    if (t0 >= R) return;           // tile entirely past the active rows

    __shared__ float As[2][BKT][AS_STR];
    __shared__ __align__(16) float Bs[2][BKT][BNT];
    __shared__ float red[BMT][17];

    const int tid = threadIdx.x;
    const int tx = tid & 15, ty = tid >> 4;

    const int aRow0 = tid >> 2;
    const int aRow1 = aRow0 + 64;
    const int aCol  = (tid & 3) * 4;
    const int bRow0 = tid >> 5;
    const int bRow1 = bRow0 + 8;
    const int bCol  = (tid & 31) * 4;

    const int m0r = g_rowmap[t0 + aRow0];
    const int m1r = g_rowmap[t0 + aRow1];
    const float* aP0 = A + (size_t)m0r * K_DIM + aCol;
    const float* aP1 = A + (size_t)m1r * K_DIM + aCol;

    float rowacc[8];
#pragma unroll
    for (int i = 0; i < 8; i++) rowacc[i] = 0.f;
    const float b2s = b2[0];

    for (int n0 = 0; n0 < N_DIM; n0 += BNT) {
        u64 acc2[8][4];
#pragma unroll
        for (int i = 0; i < 8; i++)
#pragma unroll
            for (int j = 0; j < 4; j++) acc2[i][j] = 0ull;

        float4 aR0, aR1, bR0, bR1;
        aR0 = *(const float4*)(aP0);
        aR1 = *(const float4*)(aP1);
        bR0 = *(const float4*)(W1 + (size_t)bRow0 * N_DIM + n0 + bCol);
        bR1 = *(const float4*)(W1 + (size_t)bRow1 * N_DIM + n0 + bCol);
        As[0][aCol + 0][aRow0] = aR0.x; As[0][aCol + 1][aRow0] = aR0.y;
        As[0][aCol + 2][aRow0] = aR0.z; As[0][aCol + 3][aRow0] = aR0.w;
        As[0][aCol + 0][aRow1] = aR1.x; As[0][aCol + 1][aRow1] = aR1.y;
        As[0][aCol + 2][aRow1] = aR1.z; As[0][aCol + 3][aRow1] = aR1.w;
        *(float4*)&Bs[0][bRow0][bCol] = bR0;
        *(float4*)&Bs[0][bRow1][bCol] = bR1;
        __syncthreads();

        for (int kt = 0; kt < KTILES; kt++) {
            const int cur = kt & 1;
            if (kt + 1 < KTILES) {
                const int kb = (kt + 1) * BKT;
                aR0 = *(const float4*)(aP0 + kb);
                aR1 = *(const float4*)(aP1 + kb);
                bR0 = *(const float4*)(W1 + (size_t)(kb + bRow0) * N_DIM + n0 + bCol);
                bR1 = *(const float4*)(W1 + (size_t)(kb + bRow1) * N_DIM + n0 + bCol);
            }
#pragma unroll
            for (int kk = 0; kk < BKT; kk++) {
                float4 a0 = *(const float4*)&As[cur][kk][ty * 8];
                float4 a1 = *(const float4*)&As[cur][kk][ty * 8 + 4];
                const u64* bp = (const u64*)&Bs[cur][kk][tx * 8];
                u64 b0 = bp[0], b1v = bp[1], b2v = bp[2], b3 = bp[3];
                float av[8] = {a0.x, a0.y, a0.z, a0.w, a1.x, a1.y, a1.z, a1.w};
#pragma unroll
                for (int i = 0; i < 8; i++) {
                    u64 ad = dupf(av[i]);
                    acc2[i][0] = fma2(ad, b0,  acc2[i][0]);
                    acc2[i][1] = fma2(ad, b1v, acc2[i][1]);
                    acc2[i][2] = fma2(ad, b2v, acc2[i][2]);
                    acc2[i][3] = fma2(ad, b3,  acc2[i][3]);
                }
            }
            if (kt + 1 < KTILES) {
                const int nb = cur ^ 1;
                As[nb][aCol + 0][aRow0] = aR0.x; As[nb][aCol + 1][aRow0] = aR0.y;
                As[nb][aCol + 2][aRow0] = aR0.z; As[nb][aCol + 3][aRow0] = aR0.w;
                As[nb][aCol + 0][aRow1] = aR1.x; As[nb][aCol + 1][aRow1] = aR1.y;
                As[nb][aCol + 2][aRow1] = aR1.z; As[nb][aCol + 3][aRow1] = aR1.w;
                *(float4*)&Bs[nb][bRow0][bCol] = bR0;
                *(float4*)&Bs[nb][bRow1][bCol] = bR1;
                __syncthreads();
            }
        }

        float b1r[8], w2r[8];
#pragma unroll
        for (int j = 0; j < 8; j++) {
            b1r[j] = b1[n0 + tx * 8 + j];
            w2r[j] = w2[n0 + tx * 8 + j];
        }
#pragma unroll
        for (int i = 0; i < 8; i++)
#pragma unroll
            for (int j2 = 0; j2 < 4; j2++) {
                float clo, chi;
                unpk(acc2[i][j2], clo, chi);
                float h0 = fmaxf(clo + b1r[j2 * 2], 0.f);
                float h1 = fmaxf(chi + b1r[j2 * 2 + 1], 0.f);
                rowacc[i] = fmaf(h0, w2r[j2 * 2], rowacc[i]);
                rowacc[i] = fmaf(h1, w2r[j2 * 2 + 1], rowacc[i]);
            }
        __syncthreads();
    }

#pragma unroll
    for (int i = 0; i < 8; i++) red[ty * 8 + i][tx] = rowacc[i];
    __syncthreads();
    if (tid < BMT && t0 + tid < R) {
        float s = 0.f;
#pragma unroll
        for (int x = 0; x < 16; x++) s += red[tid][x];
        float arg = s + b2s;
        g_w[g_rowmap[t0 + tid]] = 1.0f / (1.0f + expf(-arg));
    }
}

// ---------------- K2: scalar CIF scan per batch -----------------------------
__global__ void k2_scan(float* __restrict__ out_marks,
                        float* __restrict__ out_quantity,
                        int write_extras)
{
    const int b = blockIdx.x;
    const int lane = threadIdx.x;
    const int L = g_len[b];

    float prev_w = 0.f, quantity = 0.f, seg_c0 = 0.f, last_w = 0.f;
    int seg_t0 = 0, r = 0;

    for (int chunk = 0; chunk < T_DIM; chunk += 32) {
        float wv = g_w[(chunk + lane) * B_DIM + b];
        float mymark = 0.f;
#pragma unroll 1
        for (int j = 0; j < 32; j++) {
            const int t = chunk + j;
            float w = __shfl_sync(0xffffffffu, wv, j);
            float mark = 0.f;
            if (t < L) {
                quantity += w;
                if (t == 0) seg_c0 = w;
                bool fired = (prev_w + w >= 1.0f);
                if (fired) {
                    float remained = 1.0f - prev_w;
                    if (lane == 0) {
                        int idx = b * T_DIM + r;
                        g_rt0[idx] = seg_t0; g_rt1[idx] = t;
                        g_rc0[idx] = seg_c0; g_rc1[idx] = remained;
                        g_rmult[idx] = 1.0f;
                    }
                    r++;
                    prev_w = w - remained;
                    seg_t0 = t;
                    seg_c0 = w - remained;
                    mark = 1.f;
                } else {
                    prev_w = w + prev_w;
                }
                last_w = w;
            } else if (t == L) {
                if (prev_w > 0.6f) {
                    if (lane == 0) {
                        int idx = b * T_DIM + r;
                        g_rt0[idx] = seg_t0; g_rt1[idx] = L - 1;
                        g_rc0[idx] = seg_c0; g_rc1[idx] = last_w;
                        g_rmult[idx] = 1.0f / (prev_w + 1e-10f);
                    }
                    r++;
                    mark = 1.f;
                }
            }
            if (lane == j) mymark = mark;
        }
        if (write_extras) out_marks[b * T_DIM + chunk + lane] = mymark;
    }
    if (lane == 0) {
        g_nrows[b] = r;
        if (write_extras) out_quantity[b] = quantity;
    }
}

// ---------------- K3: segment sums in compacted order -----------------------
__global__ __launch_bounds__(128) void k3_rows(
    const float* __restrict__ x,
    float* __restrict__ out_cif,
    float* __restrict__ out_mask,
    int write_extras)
{
    const int r = blockIdx.x, b = blockIdx.y;
    const int tid = threadIdx.x;
    const int nr = g_nrows[b];

    float4 acc = make_float4(0.f, 0.f, 0.f, 0.f);
    if (r < nr) {
        const int idx = b * T_DIM + r;
        const int t0 = g_rt0[idx], t1 = g_rt1[idx];
        const float c0 = g_rc0[idx], c1 = g_rc1[idx], mult = g_rmult[idx];
        const float* xb = x + (size_t)b * E_DIM + tid * 4;
        const size_t tstride = (size_t)B_DIM * E_DIM;

        float4 v = *(const float4*)(xb + (size_t)t0 * tstride);
        acc.x = c0 * v.x; acc.y = c0 * v.y; acc.z = c0 * v.z; acc.w = c0 * v.w;
        for (int t = t0 + 1; t < t1; t++) {
            float w = g_w[t * B_DIM + b];
            v = *(const float4*)(xb + (size_t)t * tstride);
            acc.x = fmaf(w, v.x, acc.x); acc.y = fmaf(w, v.y, acc.y);
            acc.z = fmaf(w, v.z, acc.z); acc.w = fmaf(w, v.w, acc.w);
        }
        if (t1 > t0) {
            v = *(const float4*)(xb + (size_t)t1 * tstride);
            acc.x = fmaf(c1, v.x, acc.x); acc.y = fmaf(c1, v.y, acc.y);
            acc.z = fmaf(c1, v.z, acc.z); acc.w = fmaf(c1, v.w, acc.w);
        }
        acc.x *= mult; acc.y *= mult; acc.z *= mult; acc.w *= mult;
    }
    *(float4*)(out_cif + ((size_t)(b * T_DIM + r)) * E_DIM + tid * 4) = acc;
    if (write_extras && tid == 0) out_mask[b * T_DIM + r] = (r < nr) ? 1.f : 0.f;
}

// ---------------- launch ----------------------------------------------------
extern "C" void kernel_launch(void* const* d_in, const int* in_sizes, int n_in,
                              void* d_out, int out_size)
{
    const float* enc = (const float*)d_in[0];
    const void*  mask = d_in[1];
    const float* dense_w = (const float*)d_in[2];
    const float* dense_b = (const float*)d_in[3];
    const float* wproj_w = (const float*)d_in[4];
    const float* wproj_b = (const float*)d_in[5];
    float* out = (float*)d_out;

    const int cif_elems = B_DIM * T_DIM * E_DIM;
    const int full = cif_elems + B_DIM * T_DIM + B_DIM + B_DIM * T_DIM;
    const int extras = (out_size >= full) ? 1 : 0;

    float* out_mask   = out + cif_elems;
    float* out_q      = out_mask + B_DIM * T_DIM;
    float* out_marks  = out_q + B_DIM;

    k0a_mask<<<1, 1024>>>(mask);
    k0b_rowmap<<<B_DIM + 1, 256>>>();
    k1_gemm<<<M_DIM / BMT, 256>>>(enc, dense_w, dense_b, wproj_w, wproj_b);
    k2_scan<<<B_DIM, 32>>>(out_marks, out_q, extras);
    k3_rows<<<dim3(T_DIM, B_DIM), 128>>>(enc, out, out_mask, extras);
}

// round 11
// speedup vs baseline: 1.1389x; 1.1338x over previous
#include <cuda_runtime.h>
#include <cstdint>
#include <cstddef>

#define T_DIM 2048
#define B_DIM 32
#define E_DIM 512
#define N_DIM 512
#define K_DIM 512
#define M_DIM (T_DIM * B_DIM)   // 65536 rows, row m = t*B + b

// ---------------- device scratch ----------------
__device__ float g_w[M_DIM];
__device__ int   g_len[B_DIM];
__device__ int   g_nrows[B_DIM];
__device__ int   g_rt0[B_DIM * T_DIM];
__device__ int   g_rt1[B_DIM * T_DIM];
__device__ float g_rc0[B_DIM * T_DIM];
__device__ float g_rc1[B_DIM * T_DIM];
__device__ float g_rmult[B_DIM * T_DIM];

// ---------------- f32x2 helpers ----------------
typedef unsigned long long u64;
__device__ __forceinline__ u64 fma2(u64 a, u64 b, u64 c) {
    u64 d;
    asm("fma.rn.f32x2 %0, %1, %2, %3;" : "=l"(d) : "l"(a), "l"(b), "l"(c));
    return d;
}
__device__ __forceinline__ u64 dupf(float a) {
    u64 d;
    asm("mov.b64 %0, {%1, %1};" : "=l"(d) : "f"(a));
    return d;
}
__device__ __forceinline__ void unpk(u64 v, float& lo, float& hi) {
    asm("mov.b64 {%0, %1}, %2;" : "=f"(lo), "=f"(hi) : "l"(v));
}

// ---------------- K0: mask dtype detection + lengths ------------------------
__global__ void k0_mask(const void* __restrict__ mask) {
    __shared__ int flags[3];
    int tid = threadIdx.x;
    if (tid < 3) flags[tid] = 0;
    __syncthreads();
    const unsigned* dw = (const unsigned*)mask;
    for (int i = tid; i < 16384; i += blockDim.x) {
        unsigned d = dw[i];
        if (d != 0u) {
            if (d == 1u)                flags[0] = 1;
            else if (d == 0x3F800000u)  flags[1] = 1;
            else                        flags[2] = 1;
        }
    }
    __syncthreads();
    int kind = flags[2] ? 2 : (flags[1] ? 1 : 0);
    int warp = tid >> 5, lane = tid & 31;
    int cnt = 0;
    if (kind == 2) {
        const unsigned char* p = (const unsigned char*)mask + warp * T_DIM;
        for (int t = lane; t < T_DIM; t += 32) cnt += (p[t] == 0);
    } else {
        const unsigned* p = dw + (size_t)warp * T_DIM;
        for (int t = lane; t < T_DIM; t += 32) cnt += (p[t] == 0u);
    }
    for (int o = 16; o > 0; o >>= 1) cnt += __shfl_down_sync(0xffffffffu, cnt, o);
    if (lane == 0) g_len[warp] = cnt;
}

// ---------------- K1: fused fp32 GEMM + ReLU + proj + sigmoid ---------------
// CTA (x, b): rows t in [128x, 128x+128) for batch b; early-exit if the whole
// tile is padding (t >= len[b]). Best-measured R8 variant, unchanged.
#define BMT 128
#define BNT 128
#define BKT 16
#define KTILES (K_DIM / BKT)   // 32
#define AS_STR (BMT + 4)

__global__ __launch_bounds__(256, 2) void k1_gemm(
    const float* __restrict__ A,   // [T][B][E]; row(t,b) at ((t*B)+b)*E
    const float* __restrict__ W1,  // [K][N] row-major
    const float* __restrict__ b1,  // [N]
    const float* __restrict__ w2,  // [N]
    const float* __restrict__ b2)  // [1]
{
    const int b = blockIdx.y;
    const int t0 = blockIdx.x * BMT;
    if (t0 >= g_len[b]) return;   // whole tile is padding: weights never read

    __shared__ float As[2][BKT][AS_STR];
    __shared__ __align__(16) float Bs[2][BKT][BNT];
    __shared__ float red[BMT][17];

    const int tid = threadIdx.x;
    const int tx = tid & 15, ty = tid >> 4;

    const int aRow0 = tid >> 2;
    const int aRow1 = aRow0 + 64;
    const int aCol  = (tid & 3) * 4;
    const int bRow0 = tid >> 5;
    const int bRow1 = bRow0 + 8;
    const int bCol  = (tid & 31) * 4;

    const float* aP0 = A + ((size_t)(t0 + aRow0) * B_DIM + b) * K_DIM + aCol;
    const float* aP1 = A + ((size_t)(t0 + aRow1) * B_DIM + b) * K_DIM + aCol;

    float rowacc[8];
#pragma unroll
    for (int i = 0; i < 8; i++) rowacc[i] = 0.f;
    const float b2s = b2[0];

    for (int n0 = 0; n0 < N_DIM; n0 += BNT) {
        u64 acc2[8][4];
#pragma unroll
        for (int i = 0; i < 8; i++)
#pragma unroll
            for (int j = 0; j < 4; j++) acc2[i][j] = 0ull;

        float4 aR0, aR1, bR0, bR1;
        aR0 = *(const float4*)(aP0);
        aR1 = *(const float4*)(aP1);
        bR0 = *(const float4*)(W1 + (size_t)bRow0 * N_DIM + n0 + bCol);
        bR1 = *(const float4*)(W1 + (size_t)bRow1 * N_DIM + n0 + bCol);
        As[0][aCol + 0][aRow0] = aR0.x; As[0][aCol + 1][aRow0] = aR0.y;
        As[0][aCol + 2][aRow0] = aR0.z; As[0][aCol + 3][aRow0] = aR0.w;
        As[0][aCol + 0][aRow1] = aR1.x; As[0][aCol + 1][aRow1] = aR1.y;
        As[0][aCol + 2][aRow1] = aR1.z; As[0][aCol + 3][aRow1] = aR1.w;
        *(float4*)&Bs[0][bRow0][bCol] = bR0;
        *(float4*)&Bs[0][bRow1][bCol] = bR1;
        __syncthreads();

        for (int kt = 0; kt < KTILES; kt++) {
            const int cur = kt & 1;
            if (kt + 1 < KTILES) {
                const int kb = (kt + 1) * BKT;
                aR0 = *(const float4*)(aP0 + kb);
                aR1 = *(const float4*)(aP1 + kb);
                bR0 = *(const float4*)(W1 + (size_t)(kb + bRow0) * N_DIM + n0 + bCol);
                bR1 = *(const float4*)(W1 + (size_t)(kb + bRow1) * N_DIM + n0 + bCol);
            }
#pragma unroll
            for (int kk = 0; kk < BKT; kk++) {
                float4 a0 = *(const float4*)&As[cur][kk][ty * 8];
                float4 a1 = *(const float4*)&As[cur][kk][ty * 8 + 4];
                const u64* bp = (const u64*)&Bs[cur][kk][tx * 8];
                u64 b0 = bp[0], b1v = bp[1], b2v = bp[2], b3 = bp[3];
                float av[8] = {a0.x, a0.y, a0.z, a0.w, a1.x, a1.y, a1.z, a1.w};
#pragma unroll
                for (int i = 0; i < 8; i++) {
                    u64 ad = dupf(av[i]);
                    acc2[i][0] = fma2(ad, b0,  acc2[i][0]);
                    acc2[i][1] = fma2(ad, b1v, acc2[i][1]);
                    acc2[i][2] = fma2(ad, b2v, acc2[i][2]);
                    acc2[i][3] = fma2(ad, b3,  acc2[i][3]);
                }
            }
            if (kt + 1 < KTILES) {
                const int nb = cur ^ 1;
                As[nb][aCol + 0][aRow0] = aR0.x; As[nb][aCol + 1][aRow0] = aR0.y;
                As[nb][aCol + 2][aRow0] = aR0.z; As[nb][aCol + 3][aRow0] = aR0.w;
                As[nb][aCol + 0][aRow1] = aR1.x; As[nb][aCol + 1][aRow1] = aR1.y;
                As[nb][aCol + 2][aRow1] = aR1.z; As[nb][aCol + 3][aRow1] = aR1.w;
                *(float4*)&Bs[nb][bRow0][bCol] = bR0;
                *(float4*)&Bs[nb][bRow1][bCol] = bR1;
                __syncthreads();
            }
        }

        float b1r[8], w2r[8];
#pragma unroll
        for (int j = 0; j < 8; j++) {
            b1r[j] = b1[n0 + tx * 8 + j];
            w2r[j] = w2[n0 + tx * 8 + j];
        }
#pragma unroll
        for (int i = 0; i < 8; i++)
#pragma unroll
            for (int j2 = 0; j2 < 4; j2++) {
                float clo, chi;
                unpk(acc2[i][j2], clo, chi);
                float h0 = fmaxf(clo + b1r[j2 * 2], 0.f);
                float h1 = fmaxf(chi + b1r[j2 * 2 + 1], 0.f);
                rowacc[i] = fmaf(h0, w2r[j2 * 2], rowacc[i]);
                rowacc[i] = fmaf(h1, w2r[j2 * 2 + 1], rowacc[i]);
            }
        __syncthreads();
    }

#pragma unroll
    for (int i = 0; i < 8; i++) red[ty * 8 + i][tx] = rowacc[i];
    __syncthreads();
    if (tid < BMT) {
        float s = 0.f;
#pragma unroll
        for (int x = 0; x < 16; x++) s += red[tid][x];
        float arg = s + b2s;
        g_w[(size_t)(t0 + tid) * B_DIM + b] = 1.0f / (1.0f + expf(-arg));
    }
}

// ---------------- K2: CIF scan — smem-staged, single-lane recurrence --------
// Block per batch: 256 threads stage the weight column into shared memory and
// pre-zero the marks row; thread 0 then runs the exact serial recurrence
// (same op order as before -> bit-identical outputs) at ~LDS latency.
__global__ __launch_bounds__(256) void k2_scan(float* __restrict__ out_marks,
                                               float* __restrict__ out_quantity,
                                               int write_extras)
{
    __shared__ float ws[T_DIM];
    const int b = blockIdx.x;
    const int tid = threadIdx.x;
    const int L = g_len[b];
    const int base = b * T_DIM;

    for (int t = tid; t < T_DIM; t += 256) {
        ws[t] = g_w[(size_t)t * B_DIM + b];
        if (write_extras) out_marks[base + t] = 0.f;
    }
    __syncthreads();

    if (tid == 0) {
        float prev_w = 0.f, quantity = 0.f;
        float seg_c0 = ws[0];
        int seg_t0 = 0, r = 0;
#pragma unroll 4
        for (int t = 0; t < L; t++) {
            float w = ws[t];
            quantity += w;
            float sum = prev_w + w;
            if (sum >= 1.0f) {
                float remained = 1.0f - prev_w;
                int idx = base + r;
                g_rt0[idx] = seg_t0; g_rt1[idx] = t;
                g_rc0[idx] = seg_c0; g_rc1[idx] = remained;
                g_rmult[idx] = 1.0f;
                r++;
                float nw = w - remained;
                prev_w = nw;
                seg_t0 = t;
                seg_c0 = nw;
                if (write_extras) out_marks[base + t] = 1.f;
            } else {
                prev_w = sum;
            }
        }
        if (L < T_DIM && prev_w > 0.6f) {
            int idx = base + r;
            g_rt0[idx] = seg_t0; g_rt1[idx] = L - 1;
            g_rc0[idx] = seg_c0; g_rc1[idx] = ws[L - 1];
            g_rmult[idx] = 1.0f / (prev_w + 1e-10f);
            r++;
            if (write_extras) out_marks[base + L] = 1.f;
        }
        g_nrows[b] = r;
        if (write_extras) out_quantity[b] = quantity;
    }
}

// ---------------- K3: segment sums in compacted order -----------------------
__global__ __launch_bounds__(128) void k3_rows(
    const float* __restrict__ x,
    float* __restrict__ out_cif,
    float* __restrict__ out_mask,
    int write_extras)
{
    const int r = blockIdx.x, b = blockIdx.y;
    const int tid = threadIdx.x;
    const int nr = g_nrows[b];

    float4 acc = make_float4(0.f, 0.f, 0.f, 0.f);
    if (r < nr) {
        const int idx = b * T_DIM + r;
        const int t0 = g_rt0[idx], t1 = g_rt1[idx];
        const float c0 = g_rc0[idx], c1 = g_rc1[idx], mult = g_rmult[idx];
        const float* xb = x + (size_t)b * E_DIM + tid * 4;
        const size_t tstride = (size_t)B_DIM * E_DIM;

        float4 v = *(const float4*)(xb + (size_t)t0 * tstride);
        acc.x = c0 * v.x; acc.y = c0 * v.y; acc.z = c0 * v.z; acc.w = c0 * v.w;
        for (int t = t0 + 1; t < t1; t++) {
            float w = g_w[t * B_DIM + b];
            v = *(const float4*)(xb + (size_t)t * tstride);
            acc.x = fmaf(w, v.x, acc.x); acc.y = fmaf(w, v.y, acc.y);
            acc.z = fmaf(w, v.z, acc.z); acc.w = fmaf(w, v.w, acc.w);
        }
        if (t1 > t0) {
            v = *(const float4*)(xb + (size_t)t1 * tstride);
            acc.x = fmaf(c1, v.x, acc.x); acc.y = fmaf(c1, v.y, acc.y);
            acc.z = fmaf(c1, v.z, acc.z); acc.w = fmaf(c1, v.w, acc.w);
        }
        acc.x *= mult; acc.y *= mult; acc.z *= mult; acc.w *= mult;
    }
    *(float4*)(out_cif + ((size_t)(b * T_DIM + r)) * E_DIM + tid * 4) = acc;
    if (write_extras && tid == 0) out_mask[b * T_DIM + r] = (r < nr) ? 1.f : 0.f;
}

// ---------------- launch ----------------------------------------------------
extern "C" void kernel_launch(void* const* d_in, const int* in_sizes, int n_in,
                              void* d_out, int out_size)
{
    const float* enc = (const float*)d_in[0];
    const void*  mask = d_in[1];
    const float* dense_w = (const float*)d_in[2];
    const float* dense_b = (const float*)d_in[3];
    const float* wproj_w = (const float*)d_in[4];
    const float* wproj_b = (const float*)d_in[5];
    float* out = (float*)d_out;

    const int cif_elems = B_DIM * T_DIM * E_DIM;
    const int full = cif_elems + B_DIM * T_DIM + B_DIM + B_DIM * T_DIM;
    const int extras = (out_size >= full) ? 1 : 0;

    float* out_mask   = out + cif_elems;
    float* out_q      = out_mask + B_DIM * T_DIM;
    float* out_marks  = out_q + B_DIM;

    k0_mask<<<1, 1024>>>(mask);
    k1_gemm<<<dim3(T_DIM / BMT, B_DIM), 256>>>(enc, dense_w, dense_b, wproj_w, wproj_b);
    k2_scan<<<B_DIM, 256>>>(out_marks, out_q, extras);
    k3_rows<<<dim3(T_DIM, B_DIM), 128>>>(enc, out, out_mask, extras);
}

// round 13
// speedup vs baseline: 1.1745x; 1.0313x over previous
#include <cuda_runtime.h>
#include <cstdint>
#include <cstddef>

#define T_DIM 2048
#define B_DIM 32
#define E_DIM 512
#define N_DIM 512
#define K_DIM 512
#define M_DIM (T_DIM * B_DIM)   // 65536 rows, row m = t*B + b

// ---------------- device scratch ----------------
__device__ float g_w[M_DIM];
__device__ int   g_len[B_DIM];
__device__ int   g_nrows[B_DIM];
__device__ int   g_rt0[B_DIM * T_DIM];
__device__ int   g_rt1[B_DIM * T_DIM];
__device__ float g_rc0[B_DIM * T_DIM];
__device__ float g_rc1[B_DIM * T_DIM];
__device__ float g_rmult[B_DIM * T_DIM];

// ---------------- f32x2 helpers ----------------
typedef unsigned long long u64;
__device__ __forceinline__ u64 fma2(u64 a, u64 b, u64 c) {
    u64 d;
    asm("fma.rn.f32x2 %0, %1, %2, %3;" : "=l"(d) : "l"(a), "l"(b), "l"(c));
    return d;
}
__device__ __forceinline__ u64 dupf(float a) {
    u64 d;
    asm("mov.b64 %0, {%1, %1};" : "=l"(d) : "f"(a));
    return d;
}
__device__ __forceinline__ void unpk(u64 v, float& lo, float& hi) {
    asm("mov.b64 {%0, %1}, %2;" : "=f"(lo), "=f"(hi) : "l"(v));
}

// ---------------- K0: mask dtype detection + lengths ------------------------
__global__ void k0_mask(const void* __restrict__ mask) {
    __shared__ int flags[3];
    int tid = threadIdx.x;
    if (tid < 3) flags[tid] = 0;
    __syncthreads();
    const unsigned* dw = (const unsigned*)mask;
    for (int i = tid; i < 16384; i += blockDim.x) {
        unsigned d = dw[i];
        if (d != 0u) {
            if (d == 1u)                flags[0] = 1;
            else if (d == 0x3F800000u)  flags[1] = 1;
            else                        flags[2] = 1;
        }
    }
    __syncthreads();
    int kind = flags[2] ? 2 : (flags[1] ? 1 : 0);
    int warp = tid >> 5, lane = tid & 31;
    int cnt = 0;
    if (kind == 2) {
        const unsigned char* p = (const unsigned char*)mask + warp * T_DIM;
        for (int t = lane; t < T_DIM; t += 32) cnt += (p[t] == 0);
    } else {
        const unsigned* p = dw + (size_t)warp * T_DIM;
        for (int t = lane; t < T_DIM; t += 32) cnt += (p[t] == 0u);
    }
    for (int o = 16; o > 0; o >>= 1) cnt += __shfl_down_sync(0xffffffffu, cnt, o);
    if (lane == 0) g_len[warp] = cnt;
}

// ---------------- K_zero: zero-fill outputs (runs concurrent with k1) -------
__global__ __launch_bounds__(256) void k_zero(float* __restrict__ out_cif,
                                              float* __restrict__ out_mask,
                                              float* __restrict__ out_marks,
                                              int extras)
{
    const size_t stride = (size_t)gridDim.x * blockDim.x;
    const size_t i0 = (size_t)blockIdx.x * blockDim.x + threadIdx.x;
    const float4 z = make_float4(0.f, 0.f, 0.f, 0.f);
    float4* p = (float4*)out_cif;
    const size_t n4 = (size_t)M_DIM * E_DIM / 4;
    for (size_t j = i0; j < n4; j += stride) p[j] = z;
    if (extras) {
        float4* pm = (float4*)out_mask;
        float4* pk = (float4*)out_marks;
        for (size_t j = i0; j < M_DIM / 4; j += stride) { pm[j] = z; pk[j] = z; }
    }
}

// ---------------- K1: fused fp32 GEMM + ReLU + proj + sigmoid ---------------
#define BMT 128
#define BNT 128
#define BKT 16
#define KTILES (K_DIM / BKT)   // 32
#define AS_STR (BMT + 4)

__global__ __launch_bounds__(256, 2) void k1_gemm(
    const float* __restrict__ A,   // [T][B][E]; row(t,b) at ((t*B)+b)*E
    const float* __restrict__ W1,  // [K][N] row-major
    const float* __restrict__ b1,  // [N]
    const float* __restrict__ w2,  // [N]
    const float* __restrict__ b2)  // [1]
{
    const int b = blockIdx.y;
    const int t0 = blockIdx.x * BMT;
    if (t0 >= g_len[b]) return;   // whole tile is padding: weights never read

    __shared__ float As[2][BKT][AS_STR];
    __shared__ __align__(16) float Bs[2][BKT][BNT];
    __shared__ float red[BMT][17];

    const int tid = threadIdx.x;
    const int tx = tid & 15, ty = tid >> 4;

    const int aRow0 = tid >> 2;
    const int aRow1 = aRow0 + 64;
    const int aCol  = (tid & 3) * 4;
    const int bRow0 = tid >> 5;
    const int bRow1 = bRow0 + 8;
    const int bCol  = (tid & 31) * 4;

    const float* aP0 = A + ((size_t)(t0 + aRow0) * B_DIM + b) * K_DIM + aCol;
    const float* aP1 = A + ((size_t)(t0 + aRow1) * B_DIM + b) * K_DIM + aCol;

    float rowacc[8];
#pragma unroll
    for (int i = 0; i < 8; i++) rowacc[i] = 0.f;
    const float b2s = b2[0];

    for (int n0 = 0; n0 < N_DIM; n0 += BNT) {
        u64 acc2[8][4];
#pragma unroll
        for (int i = 0; i < 8; i++)
#pragma unroll
            for (int j = 0; j < 4; j++) acc2[i][j] = 0ull;

        float4 aR0, aR1, bR0, bR1;
        aR0 = *(const float4*)(aP0);
        aR1 = *(const float4*)(aP1);
        bR0 = *(const float4*)(W1 + (size_t)bRow0 * N_DIM + n0 + bCol);
        bR1 = *(const float4*)(W1 + (size_t)bRow1 * N_DIM + n0 + bCol);
        As[0][aCol + 0][aRow0] = aR0.x; As[0][aCol + 1][aRow0] = aR0.y;
        As[0][aCol + 2][aRow0] = aR0.z; As[0][aCol + 3][aRow0] = aR0.w;
        As[0][aCol + 0][aRow1] = aR1.x; As[0][aCol + 1][aRow1] = aR1.y;
        As[0][aCol + 2][aRow1] = aR1.z; As[0][aCol + 3][aRow1] = aR1.w;
        *(float4*)&Bs[0][bRow0][bCol] = bR0;
        *(float4*)&Bs[0][bRow1][bCol] = bR1;
        __syncthreads();

        for (int kt = 0; kt < KTILES; kt++) {
            const int cur = kt & 1;
            if (kt + 1 < KTILES) {
                const int kb = (kt + 1) * BKT;
                aR0 = *(const float4*)(aP0 + kb);
                aR1 = *(const float4*)(aP1 + kb);
                bR0 = *(const float4*)(W1 + (size_t)(kb + bRow0) * N_DIM + n0 + bCol);
                bR1 = *(const float4*)(W1 + (size_t)(kb + bRow1) * N_DIM + n0 + bCol);
            }
#pragma unroll
            for (int kk = 0; kk < BKT; kk++) {
                float4 a0 = *(const float4*)&As[cur][kk][ty * 8];
                float4 a1 = *(const float4*)&As[cur][kk][ty * 8 + 4];
                const u64* bp = (const u64*)&Bs[cur][kk][tx * 8];
                u64 b0 = bp[0], b1v = bp[1], b2v = bp[2], b3 = bp[3];
                float av[8] = {a0.x, a0.y, a0.z, a0.w, a1.x, a1.y, a1.z, a1.w};
#pragma unroll
                for (int i = 0; i < 8; i++) {
                    u64 ad = dupf(av[i]);
                    acc2[i][0] = fma2(ad, b0,  acc2[i][0]);
                    acc2[i][1] = fma2(ad, b1v, acc2[i][1]);
                    acc2[i][2] = fma2(ad, b2v, acc2[i][2]);
                    acc2[i][3] = fma2(ad, b3,  acc2[i][3]);
                }
            }
            if (kt + 1 < KTILES) {
                const int nb = cur ^ 1;
                As[nb][aCol + 0][aRow0] = aR0.x; As[nb][aCol + 1][aRow0] = aR0.y;
                As[nb][aCol + 2][aRow0] = aR0.z; As[nb][aCol + 3][aRow0] = aR0.w;
                As[nb][aCol + 0][aRow1] = aR1.x; As[nb][aCol + 1][aRow1] = aR1.y;
                As[nb][aCol + 2][aRow1] = aR1.z; As[nb][aCol + 3][aRow1] = aR1.w;
                *(float4*)&Bs[nb][bRow0][bCol] = bR0;
                *(float4*)&Bs[nb][bRow1][bCol] = bR1;
                __syncthreads();
            }
        }

        float b1r[8], w2r[8];
#pragma unroll
        for (int j = 0; j < 8; j++) {
            b1r[j] = b1[n0 + tx * 8 + j];
            w2r[j] = w2[n0 + tx * 8 + j];
        }
#pragma unroll
        for (int i = 0; i < 8; i++)
#pragma unroll
            for (int j2 = 0; j2 < 4; j2++) {
                float clo, chi;
                unpk(acc2[i][j2], clo, chi);
                float h0 = fmaxf(clo + b1r[j2 * 2], 0.f);
                float h1 = fmaxf(chi + b1r[j2 * 2 + 1], 0.f);
                rowacc[i] = fmaf(h0, w2r[j2 * 2], rowacc[i]);
                rowacc[i] = fmaf(h1, w2r[j2 * 2 + 1], rowacc[i]);
            }
        __syncthreads();
    }

#pragma unroll
    for (int i = 0; i < 8; i++) red[ty * 8 + i][tx] = rowacc[i];
    __syncthreads();
    if (tid < BMT) {
        float s = 0.f;
#pragma unroll
        for (int x = 0; x < 16; x++) s += red[tid][x];
        float arg = s + b2s;
        g_w[(size_t)(t0 + tid) * B_DIM + b] = 1.0f / (1.0f + expf(-arg));
    }
}

// ---------------- K2: CIF scan — branchless serial + parallel record emit ---
// Phase 1 (thread 0): straight-line recurrence, bit-exact op order vs the
// reference (alt = w - (1 - prev)); stores prev-after and fire bits to smem.
// Phase 2 (parallel): popc/prefix -> fireIdx; records derived exactly.
__global__ __launch_bounds__(256) void k2_scan(float* __restrict__ out_marks,
                                               float* __restrict__ out_quantity,
                                               int write_extras)
{
    __shared__ float ws[T_DIM];
    __shared__ float prevA[T_DIM];
    __shared__ int   fireIdx[T_DIM];
    __shared__ unsigned fireM[64];
    __shared__ int wpre[65];

    const int b = blockIdx.x;
    const int tid = threadIdx.x;
    const int L = g_len[b];
    const int base = b * T_DIM;

    for (int t = tid; t < T_DIM; t += 256)
        ws[t] = g_w[(size_t)t * B_DIM + b];
    if (tid < 64) fireM[tid] = 0u;
    __syncthreads();

    float quantity = 0.f;
    if (tid == 0) {
        float prev = 0.f;
        unsigned mbits = 0u;
        for (int t = 0; t < L; t++) {
            float w = ws[t];
            float remained = 1.0f - prev;
            float sum = prev + w;
            float alt = w - remained;
            bool fired = (sum >= 1.0f);
            prev = fired ? alt : sum;
            quantity += w;
            prevA[t] = prev;
            unsigned bit = fired ? (1u << (t & 31)) : 0u;
            mbits = ((t & 31) == 0) ? bit : (mbits | bit);
            fireM[t >> 5] = mbits;
        }
    }
    __syncthreads();
    if (tid == 0) {
        int acc = 0;
        for (int i = 0; i < 64; i++) { wpre[i] = acc; acc += __popc(fireM[i]); }
        wpre[64] = acc;
    }
    __syncthreads();
    if (tid < 64) {
        unsigned bits = fireM[tid];
        int o = wpre[tid];
        while (bits) {
            int bb = __ffs(bits) - 1;
            fireIdx[o++] = tid * 32 + bb;
            bits &= bits - 1;
        }
    }
    __syncthreads();

    const int Rf = wpre[64];
    for (int r = tid; r < Rf; r += 256) {
        int t1 = fireIdx[r];
        int t0 = (r == 0) ? 0 : fireIdx[r - 1];
        float c0 = (r == 0) ? ws[0] : prevA[t0];
        float c1 = (t1 > 0) ? (1.0f - prevA[t1 - 1]) : 1.0f;
        int idx = base + r;
        g_rt0[idx] = t0; g_rt1[idx] = t1;
        g_rc0[idx] = c0; g_rc1[idx] = c1;
        g_rmult[idx] = 1.0f;
        if (write_extras) out_marks[base + t1] = 1.f;
    }
    if (tid == 0) {
        int r = Rf;
        float prevL = prevA[L - 1];   // L >= T/2 >= 1
        if (L < T_DIM && prevL > 0.6f) {
            int t0 = Rf ? fireIdx[Rf - 1] : 0;
            float c0 = Rf ? prevA[t0] : ws[0];
            int idx = base + r;
            g_rt0[idx] = t0; g_rt1[idx] = L - 1;
            g_rc0[idx] = c0; g_rc1[idx] = ws[L - 1];
            g_rmult[idx] = 1.0f / (prevL + 1e-10f);
            if (write_extras) out_marks[base + L] = 1.f;
            r++;
        }
        g_nrows[b] = r;
        if (write_extras) out_quantity[b] = quantity;
    }
}

// ---------------- K3: segment sums, fired rows only (zeros pre-filled) ------
__global__ __launch_bounds__(128) void k3_rows(
    const float* __restrict__ x,
    float* __restrict__ out_cif,
    float* __restrict__ out_mask,
    int write_extras)
{
    const int r = blockIdx.x, b = blockIdx.y;
    const int tid = threadIdx.x;
    if (r >= g_nrows[b]) return;

    const int idx = b * T_DIM + r;
    const int t0 = g_rt0[idx], t1 = g_rt1[idx];
    const float c0 = g_rc0[idx], c1 = g_rc1[idx], mult = g_rmult[idx];
    const float* xb = x + (size_t)b * E_DIM + tid * 4;
    const size_t tstride = (size_t)B_DIM * E_DIM;

    float4 acc;
    float4 v = *(const float4*)(xb + (size_t)t0 * tstride);
    acc.x = c0 * v.x; acc.y = c0 * v.y; acc.z = c0 * v.z; acc.w = c0 * v.w;
    for (int t = t0 + 1; t < t1; t++) {
        float w = g_w[t * B_DIM + b];
        v = *(const float4*)(xb + (size_t)t * tstride);
        acc.x = fmaf(w, v.x, acc.x); acc.y = fmaf(w, v.y, acc.y);
        acc.z = fmaf(w, v.z, acc.z); acc.w = fmaf(w, v.w, acc.w);
    }
    if (t1 > t0) {
        v = *(const float4*)(xb + (size_t)t1 * tstride);
        acc.x = fmaf(c1, v.x, acc.x); acc.y = fmaf(c1, v.y, acc.y);
        acc.z = fmaf(c1, v.z, acc.z); acc.w = fmaf(c1, v.w, acc.w);
    }
    acc.x *= mult; acc.y *= mult; acc.z *= mult; acc.w *= mult;
    *(float4*)(out_cif + ((size_t)(b * T_DIM + r)) * E_DIM + tid * 4) = acc;
    if (write_extras && tid == 0) out_mask[b * T_DIM + r] = 1.f;
}

// ---------------- launch ----------------------------------------------------
extern "C" void kernel_launch(void* const* d_in, const int* in_sizes, int n_in,
                              void* d_out, int out_size)
{
    const float* enc = (const float*)d_in[0];
    const void*  mask = d_in[1];
    const float* dense_w = (const float*)d_in[2];
    const float* dense_b = (const float*)d_in[3];
    const float* wproj_w = (const float*)d_in[4];
    const float* wproj_b = (const float*)d_in[5];
    float* out = (float*)d_out;

    const int cif_elems = B_DIM * T_DIM * E_DIM;
    const int full = cif_elems + B_DIM * T_DIM + B_DIM + B_DIM * T_DIM;
    const int extras = (out_size >= full) ? 1 : 0;

    float* out_mask   = out + cif_elems;
    float* out_q      = out_mask + B_DIM * T_DIM;
    float* out_marks  = out_q + B_DIM;

    // side stream for the zero-fill, forked/joined via events (graph-capturable)
    cudaStream_t s;
    cudaStreamCreateWithFlags(&s, cudaStreamNonBlocking);
    cudaEvent_t evF, evJ;
    cudaEventCreateWithFlags(&evF, cudaEventDisableTiming);
    cudaEventCreateWithFlags(&evJ, cudaEventDisableTiming);

    cudaEventRecord(evF, 0);
    cudaStreamWaitEvent(s, evF, 0);
    k_zero<<<1024, 256, 0, s>>>(out, out_mask, out_marks, extras);
    cudaEventRecord(evJ, s);

    k0_mask<<<1, 1024>>>(mask);
    k1_gemm<<<dim3(T_DIM / BMT, B_DIM), 256>>>(enc, dense_w, dense_b, wproj_w, wproj_b);
    k2_scan<<<B_DIM, 256>>>(out_marks, out_q, extras);
    cudaStreamWaitEvent(0, evJ, 0);
    k3_rows<<<dim3(T_DIM, B_DIM), 128>>>(enc, out, out_mask, extras);
}

// round 14
// speedup vs baseline: 1.2146x; 1.0342x over previous
#include <cuda_runtime.h>
#include <cstdint>
#include <cstddef>

#define T_DIM 2048
#define B_DIM 32
#define E_DIM 512
#define N_DIM 512
#define K_DIM 512
#define M_DIM (T_DIM * B_DIM)   // 65536 rows, row m = t*B + b

// ---------------- device scratch ----------------
__device__ float g_w[M_DIM];
__device__ int   g_len[B_DIM];
__device__ int   g_nrows[B_DIM];
__device__ int   g_rt0[B_DIM * T_DIM];
__device__ int   g_rt1[B_DIM * T_DIM];
__device__ float g_rc0[B_DIM * T_DIM];
__device__ float g_rc1[B_DIM * T_DIM];
__device__ float g_rmult[B_DIM * T_DIM];

// ---------------- f32x2 helpers ----------------
typedef unsigned long long u64;
__device__ __forceinline__ u64 fma2(u64 a, u64 b, u64 c) {
    u64 d;
    asm("fma.rn.f32x2 %0, %1, %2, %3;" : "=l"(d) : "l"(a), "l"(b), "l"(c));
    return d;
}
__device__ __forceinline__ u64 dupf(float a) {
    u64 d;
    asm("mov.b64 %0, {%1, %1};" : "=l"(d) : "f"(a));
    return d;
}
__device__ __forceinline__ void unpk(u64 v, float& lo, float& hi) {
    asm("mov.b64 {%0, %1}, %2;" : "=f"(lo), "=f"(hi) : "l"(v));
}

// ---------------- K0: mask dtype detection + lengths ------------------------
__global__ void k0_mask(const void* __restrict__ mask) {
    __shared__ int flags[3];
    int tid = threadIdx.x;
    if (tid < 3) flags[tid] = 0;
    __syncthreads();
    const unsigned* dw = (const unsigned*)mask;
    for (int i = tid; i < 16384; i += blockDim.x) {
        unsigned d = dw[i];
        if (d != 0u) {
            if (d == 1u)                flags[0] = 1;
            else if (d == 0x3F800000u)  flags[1] = 1;
            else                        flags[2] = 1;
        }
    }
    __syncthreads();
    int kind = flags[2] ? 2 : (flags[1] ? 1 : 0);
    int warp = tid >> 5, lane = tid & 31;
    int cnt = 0;
    if (kind == 2) {
        const unsigned char* p = (const unsigned char*)mask + warp * T_DIM;
        for (int t = lane; t < T_DIM; t += 32) cnt += (p[t] == 0);
    } else {
        const unsigned* p = dw + (size_t)warp * T_DIM;
        for (int t = lane; t < T_DIM; t += 32) cnt += (p[t] == 0u);
    }
    for (int o = 16; o > 0; o >>= 1) cnt += __shfl_down_sync(0xffffffffu, cnt, o);
    if (lane == 0) g_len[warp] = cnt;
}

// ---------------- K_zero: zero-fill outputs (runs concurrent with k1) -------
__global__ __launch_bounds__(256) void k_zero(float* __restrict__ out_cif,
                                              float* __restrict__ out_mask,
                                              float* __restrict__ out_marks,
                                              int extras)
{
    const size_t stride = (size_t)gridDim.x * blockDim.x;
    const size_t i0 = (size_t)blockIdx.x * blockDim.x + threadIdx.x;
    const float4 z = make_float4(0.f, 0.f, 0.f, 0.f);
    float4* p = (float4*)out_cif;
    const size_t n4 = (size_t)M_DIM * E_DIM / 4;
    for (size_t j = i0; j < n4; j += stride) p[j] = z;
    if (extras) {
        float4* pm = (float4*)out_mask;
        float4* pk = (float4*)out_marks;
        for (size_t j = i0; j < M_DIM / 4; j += stride) { pm[j] = z; pk[j] = z; }
    }
}

// ---------------- K1: fused fp32 GEMM + ReLU + proj + sigmoid ---------------
#define BMT 128
#define BNT 128
#define BKT 16
#define KTILES (K_DIM / BKT)   // 32
#define AS_STR (BMT + 4)

__global__ __launch_bounds__(256, 2) void k1_gemm(
    const float* __restrict__ A,   // [T][B][E]; row(t,b) at ((t*B)+b)*E
    const float* __restrict__ W1,  // [K][N] row-major
    const float* __restrict__ b1,  // [N]
    const float* __restrict__ w2,  // [N]
    const float* __restrict__ b2)  // [1]
{
    const int b = blockIdx.y;
    const int t0 = blockIdx.x * BMT;
    if (t0 >= g_len[b]) return;   // whole tile is padding: weights never read

    __shared__ float As[2][BKT][AS_STR];
    __shared__ __align__(16) float Bs[2][BKT][BNT];
    __shared__ float red[BMT][17];

    const int tid = threadIdx.x;
    const int tx = tid & 15, ty = tid >> 4;

    const int aRow0 = tid >> 2;
    const int aRow1 = aRow0 + 64;
    const int aCol  = (tid & 3) * 4;
    const int bRow0 = tid >> 5;
    const int bRow1 = bRow0 + 8;
    const int bCol  = (tid & 31) * 4;

    const float* aP0 = A + ((size_t)(t0 + aRow0) * B_DIM + b) * K_DIM + aCol;
    const float* aP1 = A + ((size_t)(t0 + aRow1) * B_DIM + b) * K_DIM + aCol;

    float rowacc[8];
#pragma unroll
    for (int i = 0; i < 8; i++) rowacc[i] = 0.f;
    const float b2s = b2[0];

    for (int n0 = 0; n0 < N_DIM; n0 += BNT) {
        u64 acc2[8][4];
#pragma unroll
        for (int i = 0; i < 8; i++)
#pragma unroll
            for (int j = 0; j < 4; j++) acc2[i][j] = 0ull;

        float4 aR0, aR1, bR0, bR1;
        aR0 = *(const float4*)(aP0);
        aR1 = *(const float4*)(aP1);
        bR0 = *(const float4*)(W1 + (size_t)bRow0 * N_DIM + n0 + bCol);
        bR1 = *(const float4*)(W1 + (size_t)bRow1 * N_DIM + n0 + bCol);
        As[0][aCol + 0][aRow0] = aR0.x; As[0][aCol + 1][aRow0] = aR0.y;
        As[0][aCol + 2][aRow0] = aR0.z; As[0][aCol + 3][aRow0] = aR0.w;
        As[0][aCol + 0][aRow1] = aR1.x; As[0][aCol + 1][aRow1] = aR1.y;
        As[0][aCol + 2][aRow1] = aR1.z; As[0][aCol + 3][aRow1] = aR1.w;
        *(float4*)&Bs[0][bRow0][bCol] = bR0;
        *(float4*)&Bs[0][bRow1][bCol] = bR1;
        __syncthreads();

        for (int kt = 0; kt < KTILES; kt++) {
            const int cur = kt & 1;
            if (kt + 1 < KTILES) {
                const int kb = (kt + 1) * BKT;
                aR0 = *(const float4*)(aP0 + kb);
                aR1 = *(const float4*)(aP1 + kb);
                bR0 = *(const float4*)(W1 + (size_t)(kb + bRow0) * N_DIM + n0 + bCol);
                bR1 = *(const float4*)(W1 + (size_t)(kb + bRow1) * N_DIM + n0 + bCol);
            }
#pragma unroll
            for (int kk = 0; kk < BKT; kk++) {
                float4 a0 = *(const float4*)&As[cur][kk][ty * 8];
                float4 a1 = *(const float4*)&As[cur][kk][ty * 8 + 4];
                const u64* bp = (const u64*)&Bs[cur][kk][tx * 8];
                u64 b0 = bp[0], b1v = bp[1], b2v = bp[2], b3 = bp[3];
                float av[8] = {a0.x, a0.y, a0.z, a0.w, a1.x, a1.y, a1.z, a1.w};
#pragma unroll
                for (int i = 0; i < 8; i++) {
                    u64 ad = dupf(av[i]);
                    acc2[i][0] = fma2(ad, b0,  acc2[i][0]);
                    acc2[i][1] = fma2(ad, b1v, acc2[i][1]);
                    acc2[i][2] = fma2(ad, b2v, acc2[i][2]);
                    acc2[i][3] = fma2(ad, b3,  acc2[i][3]);
                }
            }
            if (kt + 1 < KTILES) {
                const int nb = cur ^ 1;
                As[nb][aCol + 0][aRow0] = aR0.x; As[nb][aCol + 1][aRow0] = aR0.y;
                As[nb][aCol + 2][aRow0] = aR0.z; As[nb][aCol + 3][aRow0] = aR0.w;
                As[nb][aCol + 0][aRow1] = aR1.x; As[nb][aCol + 1][aRow1] = aR1.y;
                As[nb][aCol + 2][aRow1] = aR1.z; As[nb][aCol + 3][aRow1] = aR1.w;
                *(float4*)&Bs[nb][bRow0][bCol] = bR0;
                *(float4*)&Bs[nb][bRow1][bCol] = bR1;
                __syncthreads();
            }
        }

        float b1r[8], w2r[8];
#pragma unroll
        for (int j = 0; j < 8; j++) {
            b1r[j] = b1[n0 + tx * 8 + j];
            w2r[j] = w2[n0 + tx * 8 + j];
        }
#pragma unroll
        for (int i = 0; i < 8; i++)
#pragma unroll
            for (int j2 = 0; j2 < 4; j2++) {
                float clo, chi;
                unpk(acc2[i][j2], clo, chi);
                float h0 = fmaxf(clo + b1r[j2 * 2], 0.f);
                float h1 = fmaxf(chi + b1r[j2 * 2 + 1], 0.f);
                rowacc[i] = fmaf(h0, w2r[j2 * 2], rowacc[i]);
                rowacc[i] = fmaf(h1, w2r[j2 * 2 + 1], rowacc[i]);
            }
        __syncthreads();
    }

#pragma unroll
    for (int i = 0; i < 8; i++) red[ty * 8 + i][tx] = rowacc[i];
    __syncthreads();
    if (tid < BMT) {
        float s = 0.f;
#pragma unroll
        for (int x = 0; x < 16; x++) s += red[tid][x];
        float arg = s + b2s;
        g_w[(size_t)(t0 + tid) * B_DIM + b] = 1.0f / (1.0f + expf(-arg));
    }
}

// ---------------- K2: CIF scan — pipelined serial + parallel record emit ----
// Phase 1 (thread 0): 8-wide unrolled recurrence with register-prefetched
// weights; bit-exact op order vs the reference (alt = w - (1 - prev)).
// quantity computed by thread-partial sums (reduced serially, fixed order).
__global__ __launch_bounds__(256) void k2_scan(float* __restrict__ out_marks,
                                               float* __restrict__ out_quantity,
                                               int write_extras)
{
    __shared__ float ws[T_DIM];
    __shared__ float prevA[T_DIM];
    __shared__ int   fireIdx[T_DIM];
    __shared__ unsigned fireM[64];
    __shared__ int wpre[65];
    __shared__ float qp[256];

    const int b = blockIdx.x;
    const int tid = threadIdx.x;
    const int L = g_len[b];
    const int base = b * T_DIM;

    float myq = 0.f;
    for (int t = tid; t < T_DIM; t += 256) {
        float w = g_w[(size_t)t * B_DIM + b];
        ws[t] = w;
        if (t < L) myq += w;
    }
    qp[tid] = myq;
    if (tid < 64) fireM[tid] = 0u;
    __syncthreads();

    if (tid == 0) {
        float prev = 0.f;
        unsigned mbits = 0u;
        int t = 0;
        const int L8 = L & ~7;
        for (; t < L8; t += 8) {
            float4 wa = *(const float4*)&ws[t];
            float4 wb = *(const float4*)&ws[t + 4];
            float wv[8] = {wa.x, wa.y, wa.z, wa.w, wb.x, wb.y, wb.z, wb.w};
#pragma unroll
            for (int j = 0; j < 8; j++) {
                const int tt = t + j;
                float w = wv[j];
                float remained = 1.0f - prev;
                float sum = prev + w;
                float alt = w - remained;
                bool fired = (sum >= 1.0f);
                prev = fired ? alt : sum;
                prevA[tt] = prev;
                mbits |= (fired ? 1u : 0u) << (tt & 31);
                if ((tt & 31) == 31) { fireM[tt >> 5] = mbits; mbits = 0u; }
            }
        }
        for (; t < L; t++) {
            float w = ws[t];
            float remained = 1.0f - prev;
            float sum = prev + w;
            float alt = w - remained;
            bool fired = (sum >= 1.0f);
            prev = fired ? alt : sum;
            prevA[t] = prev;
            mbits |= (fired ? 1u : 0u) << (t & 31);
            if ((t & 31) == 31) { fireM[t >> 5] = mbits; mbits = 0u; }
        }
        if (L & 31) fireM[(L - 1) >> 5] = mbits;
        // prefix over fire words
        int acc = 0;
        for (int i = 0; i < 64; i++) { wpre[i] = acc; acc += __popc(fireM[i]); }
        wpre[64] = acc;
    }
    __syncthreads();
    if (tid < 64) {
        unsigned bits = fireM[tid];
        int o = wpre[tid];
        while (bits) {
            int bb = __ffs(bits) - 1;
            fireIdx[o++] = tid * 32 + bb;
            bits &= bits - 1;
        }
    }
    __syncthreads();

    const int Rf = wpre[64];
    for (int r = tid; r < Rf; r += 256) {
        int t1 = fireIdx[r];
        int t0 = (r == 0) ? 0 : fireIdx[r - 1];
        float c0 = (r == 0) ? ws[0] : prevA[t0];
        float c1 = (t1 > 0) ? (1.0f - prevA[t1 - 1]) : 1.0f;
        int idx = base + r;
        g_rt0[idx] = t0; g_rt1[idx] = t1;
        g_rc0[idx] = c0; g_rc1[idx] = c1;
        g_rmult[idx] = 1.0f;
        if (write_extras) out_marks[base + t1] = 1.f;
    }
    if (tid == 0) {
        int r = Rf;
        float prevL = prevA[L - 1];   // L >= T/2 >= 1
        if (L < T_DIM && prevL > 0.6f) {
            int t0 = Rf ? fireIdx[Rf - 1] : 0;
            float c0 = Rf ? prevA[t0] : ws[0];
            int idx = base + r;
            g_rt0[idx] = t0; g_rt1[idx] = L - 1;
            g_rc0[idx] = c0; g_rc1[idx] = ws[L - 1];
            g_rmult[idx] = 1.0f / (prevL + 1e-10f);
            if (write_extras) out_marks[base + L] = 1.f;
            r++;
        }
        g_nrows[b] = r;
        if (write_extras) {
            float q = 0.f;
            for (int i = 0; i < 256; i++) q += qp[i];
            out_quantity[b] = q;
        }
    }
}

// ---------------- K3: segment sums, fired rows only (zeros pre-filled) ------
__global__ __launch_bounds__(128) void k3_rows(
    const float* __restrict__ x,
    float* __restrict__ out_cif,
    float* __restrict__ out_mask,
    int write_extras)
{
    const int r = blockIdx.x, b = blockIdx.y;
    const int tid = threadIdx.x;
    if (r >= g_nrows[b]) return;

    const int idx = b * T_DIM + r;
    const int t0 = g_rt0[idx], t1 = g_rt1[idx];
    const float c0 = g_rc0[idx], c1 = g_rc1[idx], mult = g_rmult[idx];
    const float* xb = x + (size_t)b * E_DIM + tid * 4;
    const size_t tstride = (size_t)B_DIM * E_DIM;

    float4 acc;
    float4 v = *(const float4*)(xb + (size_t)t0 * tstride);
    acc.x = c0 * v.x; acc.y = c0 * v.y; acc.z = c0 * v.z; acc.w = c0 * v.w;
    for (int t = t0 + 1; t < t1; t++) {
        float w = g_w[t * B_DIM + b];
        v = *(const float4*)(xb + (size_t)t * tstride);
        acc.x = fmaf(w, v.x, acc.x); acc.y = fmaf(w, v.y, acc.y);
        acc.z = fmaf(w, v.z, acc.z); acc.w = fmaf(w, v.w, acc.w);
    }
    if (t1 > t0) {
        v = *(const float4*)(xb + (size_t)t1 * tstride);
        acc.x = fmaf(c1, v.x, acc.x); acc.y = fmaf(c1, v.y, acc.y);
        acc.z = fmaf(c1, v.z, acc.z); acc.w = fmaf(c1, v.w, acc.w);
    }
    acc.x *= mult; acc.y *= mult; acc.z *= mult; acc.w *= mult;
    *(float4*)(out_cif + ((size_t)(b * T_DIM + r)) * E_DIM + tid * 4) = acc;
    if (write_extras && tid == 0) out_mask[b * T_DIM + r] = 1.f;
}

// ---------------- launch ----------------------------------------------------
extern "C" void kernel_launch(void* const* d_in, const int* in_sizes, int n_in,
                              void* d_out, int out_size)
{
    const float* enc = (const float*)d_in[0];
    const void*  mask = d_in[1];
    const float* dense_w = (const float*)d_in[2];
    const float* dense_b = (const float*)d_in[3];
    const float* wproj_w = (const float*)d_in[4];
    const float* wproj_b = (const float*)d_in[5];
    float* out = (float*)d_out;

    const int cif_elems = B_DIM * T_DIM * E_DIM;
    const int full = cif_elems + B_DIM * T_DIM + B_DIM + B_DIM * T_DIM;
    const int extras = (out_size >= full) ? 1 : 0;

    float* out_mask   = out + cif_elems;
    float* out_q      = out_mask + B_DIM * T_DIM;
    float* out_marks  = out_q + B_DIM;

    // side stream for the zero-fill, forked/joined via events (graph-capturable)
    cudaStream_t s;
    cudaStreamCreateWithFlags(&s, cudaStreamNonBlocking);
    cudaEvent_t evF, evJ;
    cudaEventCreateWithFlags(&evF, cudaEventDisableTiming);
    cudaEventCreateWithFlags(&evJ, cudaEventDisableTiming);

    cudaEventRecord(evF, 0);
    cudaStreamWaitEvent(s, evF, 0);
    k_zero<<<1024, 256, 0, s>>>(out, out_mask, out_marks, extras);
    cudaEventRecord(evJ, s);

    k0_mask<<<1, 1024>>>(mask);
    k1_gemm<<<dim3(T_DIM / BMT, B_DIM), 256>>>(enc, dense_w, dense_b, wproj_w, wproj_b);
    k2_scan<<<B_DIM, 256>>>(out_marks, out_q, extras);
    cudaStreamWaitEvent(0, evJ, 0);
    k3_rows<<<dim3(T_DIM, B_DIM), 128>>>(enc, out, out_mask, extras);
}